// round 1
// baseline (speedup 1.0000x reference)
#include <cuda_runtime.h>
#include <cuda_bf16.h>
#include <cstdint>

// ChamferLoss: B=4, N=8192, D=3
//   loss = mean_{b,n} [ (min_m ||pred_bn - gt_bm||^2 + min_m ||gt_bn - pred_bm||^2) * mean_c(weight_bnc) ]
//
// Strategy: compute-bound brute force. dist = p2 + (g2 - 2 p.g). For each ref
// point we pre-transform to h = (-2gx, -2gy, -2gz, g2) in shared memory, so the
// inner loop is 3 FFMA + 1 FMNMX per pair. Each direction is just a role swap,
// and both directions are weighted by the QUERY-side w[n], so every block can
// finish its weighted partial sum locally (no global min arrays, no atomics).
// Deterministic: fixed-order block tree reduce + fixed-order final reduce.

constexpr int B = 4;
constexpr int N = 8192;
constexpr int BLOCK = 128;      // threads per block
constexpr int PPT = 2;          // query points per thread
constexpr int QPB = BLOCK * PPT;            // 256 queries per block
constexpr int TILES_PER_BD = N / QPB;       // 32
constexpr int GRID = B * 2 * TILES_PER_BD;  // 256 blocks
constexpr int TS = 1024;        // ref points per shared tile (16 KB)

__device__ float g_partial[GRID];

__global__ __launch_bounds__(BLOCK) void chamfer_kernel(
    const float* __restrict__ pred,
    const float* __restrict__ gt,
    const float* __restrict__ weight)
{
    // Decode block: which (batch, direction, query tile)
    const int qt  = blockIdx.x % TILES_PER_BD;
    const int bd  = blockIdx.x / TILES_PER_BD;
    const int dir = bd & 1;
    const int b   = bd >> 1;

    const float* __restrict__ Q = (dir ? gt   : pred) + (size_t)b * N * 3;
    const float* __restrict__ R = (dir ? pred : gt  ) + (size_t)b * N * 3;
    const float* __restrict__ W = weight + (size_t)b * N * 3;

    __shared__ float4 sh[TS];

    const int tid = threadIdx.x;
    const int q0  = qt * QPB;

    float qx[PPT], qy[PPT], qz[PPT], p2[PPT], wv[PPT], mn[PPT];
    const float INF = __int_as_float(0x7f800000);

#pragma unroll
    for (int p = 0; p < PPT; p++) {
        const int qi = q0 + tid + p * BLOCK;
        const float x = Q[3 * qi + 0];
        const float y = Q[3 * qi + 1];
        const float z = Q[3 * qi + 2];
        qx[p] = x; qy[p] = y; qz[p] = z;
        p2[p] = x * x + y * y + z * z;
        wv[p] = (W[3 * qi + 0] + W[3 * qi + 1] + W[3 * qi + 2]) * (1.0f / 3.0f);
        mn[p] = INF;
    }

    for (int t0 = 0; t0 < N; t0 += TS) {
        __syncthreads();
        // stage refs into shared as (-2gx, -2gy, -2gz, g2)
        for (int j = tid; j < TS; j += BLOCK) {
            const int m = t0 + j;
            const float gx = R[3 * m + 0];
            const float gy = R[3 * m + 1];
            const float gz = R[3 * m + 2];
            sh[j] = make_float4(-2.0f * gx, -2.0f * gy, -2.0f * gz,
                                gx * gx + gy * gy + gz * gz);
        }
        __syncthreads();

#pragma unroll 8
        for (int j = 0; j < TS; j++) {
            const float4 h = sh[j];
#pragma unroll
            for (int p = 0; p < PPT; p++) {
                float s = fmaf(qx[p], h.x, h.w);
                s = fmaf(qy[p], h.y, s);
                s = fmaf(qz[p], h.z, s);
                mn[p] = fminf(mn[p], s);
            }
        }
    }

    // local weighted sum: (p2 + min_s) * w
    float local = 0.0f;
#pragma unroll
    for (int p = 0; p < PPT; p++)
        local += (p2[p] + mn[p]) * wv[p];

    // deterministic block reduce
    __shared__ float red[BLOCK];
    red[tid] = local;
    __syncthreads();
#pragma unroll
    for (int s = BLOCK / 2; s > 0; s >>= 1) {
        if (tid < s) red[tid] += red[tid + s];
        __syncthreads();
    }
    if (tid == 0) g_partial[blockIdx.x] = red[0];
}

__global__ void chamfer_reduce_kernel(float* __restrict__ out)
{
    __shared__ float red[GRID];
    const int tid = threadIdx.x;
    red[tid] = g_partial[tid];
    __syncthreads();
#pragma unroll
    for (int s = GRID / 2; s > 0; s >>= 1) {
        if (tid < s) red[tid] += red[tid + s];
        __syncthreads();
    }
    if (tid == 0) out[0] = red[0] * (1.0f / (float)(B * N));
}

extern "C" void kernel_launch(void* const* d_in, const int* in_sizes, int n_in,
                              void* d_out, int out_size)
{
    const float* pred   = (const float*)d_in[0];
    const float* gt     = (const float*)d_in[1];
    const float* weight = (const float*)d_in[2];
    float* out = (float*)d_out;

    chamfer_kernel<<<GRID, BLOCK>>>(pred, gt, weight);
    chamfer_reduce_kernel<<<1, GRID>>>(out);
}

// round 4
// speedup vs baseline: 1.6519x; 1.6519x over previous
#include <cuda_runtime.h>
#include <cuda_bf16.h>
#include <cstdint>

// ChamferLoss B=4, N=8192, D=3.
// dist(n,m) = |q_n|^2 + (|g_m|^2 - 2 q_n . g_m). Inner loop computes
// s = g2 - 2 q.g with packed fma.rn.f32x2 (2 query points per op); |q|^2 is
// added after the min. Refs are staged in shared pre-duplicated:
//   sh[2j]   = (-2gx,-2gx,-2gy,-2gy)
//   sh[2j+1] = (-2gz,-2gz, g2 , g2 )
// so a ulonglong2 (LDS.128) load yields ready-to-use packed operands.
//
// Work decomposition: 4 batches x 2 directions x 16 query-tiles(512) x
// 8 ref-splits(1024) = 1024 uniform blocks (1.2% wave imbalance on 148 SMs).
// Ref-split partial mins go to a __device__ scratch array; kernel2 combines
// mins, adds |q|^2, applies weights, block-reduces; kernel3 does the final
// fixed-order sum. Fully deterministic, allocation-free, graph-capturable.

constexpr int B = 4;
constexpr int N = 8192;
constexpr int BLOCK = 128;
constexpr int PPT = 4;                    // queries per thread (2 f32x2 pairs)
constexpr int QPB = BLOCK * PPT;          // 512 queries per block
constexpr int QT  = N / QPB;              // 16 query tiles
constexpr int RS  = 8;                    // ref splits
constexpr int REFS_PER_RS = N / RS;       // 1024
constexpr int TS  = 512;                  // refs per shared tile (16 KB)
constexpr int GRID1 = B * 2 * QT * RS;    // 1024 blocks
constexpr int NBD = B * 2;                // 8 (batch,dir) combos

// pmin layout: [bd(8)][qt(16)][rs(8)][512]
__device__ float g_pmin[NBD * QT * RS * QPB];
__device__ float g_partial2[128];

__device__ __forceinline__ unsigned long long fma2(
    unsigned long long a, unsigned long long b, unsigned long long c)
{
    unsigned long long d;
    asm("fma.rn.f32x2 %0, %1, %2, %3;" : "=l"(d) : "l"(a), "l"(b), "l"(c));
    return d;
}

__device__ __forceinline__ unsigned long long pack2(float lo, float hi)
{
    unsigned long long d;
    asm("mov.b64 %0, {%1, %2};" : "=l"(d) : "f"(lo), "f"(hi));
    return d;
}

__device__ __forceinline__ void unpack2(unsigned long long v, float& lo, float& hi)
{
    asm("mov.b64 {%0, %1}, %2;" : "=f"(lo), "=f"(hi) : "l"(v));
}

__global__ __launch_bounds__(BLOCK) void chamfer_min_kernel(
    const float* __restrict__ pred,
    const float* __restrict__ gt)
{
    const int bx  = blockIdx.x;
    const int rs  = bx & (RS - 1);
    const int qt  = (bx >> 3) & (QT - 1);
    const int bd  = bx >> 7;
    const int dir = bd & 1;
    const int b   = bd >> 1;

    const float* __restrict__ Q = (dir ? gt   : pred) + (size_t)b * N * 3;
    const float* __restrict__ R = (dir ? pred : gt  ) + (size_t)b * N * 3;

    // sh holds TS entries of 32 bytes each:
    //   [4j..4j+1]: (-2gx,-2gx,-2gy,-2gy)  [4j+2..4j+3]: (-2gz,-2gz,g2,g2)
    __shared__ unsigned long long sh[4 * TS];

    const int tid = threadIdx.x;
    const float INF = __int_as_float(0x7f800000);

    // Queries for this thread: qt*512 + tid + k*128, k=0..3.
    unsigned long long qx[2], qy[2], qz[2];
#pragma unroll
    for (int pp = 0; pp < 2; pp++) {
        const int qa = qt * QPB + tid + (2 * pp) * BLOCK;
        const int qb = qa + BLOCK;
        qx[pp] = pack2(Q[3 * qa + 0], Q[3 * qb + 0]);
        qy[pp] = pack2(Q[3 * qa + 1], Q[3 * qb + 1]);
        qz[pp] = pack2(Q[3 * qa + 2], Q[3 * qb + 2]);
    }
    float mn0 = INF, mn1 = INF, mn2 = INF, mn3 = INF;

    const int r0 = rs * REFS_PER_RS;
    for (int t0 = r0; t0 < r0 + REFS_PER_RS; t0 += TS) {
        __syncthreads();
        for (int j = tid; j < TS; j += BLOCK) {
            const int m = t0 + j;
            const float gx = R[3 * m + 0];
            const float gy = R[3 * m + 1];
            const float gz = R[3 * m + 2];
            const float g2 = gx * gx + gy * gy + gz * gz;
            sh[4 * j + 0] = pack2(-2.0f * gx, -2.0f * gx);
            sh[4 * j + 1] = pack2(-2.0f * gy, -2.0f * gy);
            sh[4 * j + 2] = pack2(-2.0f * gz, -2.0f * gz);
            sh[4 * j + 3] = pack2(g2, g2);
        }
        __syncthreads();

        const ulonglong2* __restrict__ sh2 = reinterpret_cast<const ulonglong2*>(sh);
#pragma unroll 4
        for (int j = 0; j < TS; j++) {
            const ulonglong2 hxy = sh2[2 * j];      // (hxx, hyy)
            const ulonglong2 hzw = sh2[2 * j + 1];  // (hzz, hww)

            unsigned long long s01 = fma2(qx[0], hxy.x, hzw.y);
            unsigned long long s23 = fma2(qx[1], hxy.x, hzw.y);
            s01 = fma2(qy[0], hxy.y, s01);
            s23 = fma2(qy[1], hxy.y, s23);
            s01 = fma2(qz[0], hzw.x, s01);
            s23 = fma2(qz[1], hzw.x, s23);

            float a, bb, c, d;
            unpack2(s01, a, bb);
            unpack2(s23, c, d);
            mn0 = fminf(mn0, a);
            mn1 = fminf(mn1, bb);
            mn2 = fminf(mn2, c);
            mn3 = fminf(mn3, d);
        }
    }

    float* __restrict__ out = g_pmin + (size_t)bx * QPB;
    out[tid]             = mn0;
    out[tid + BLOCK]     = mn1;
    out[tid + 2 * BLOCK] = mn2;
    out[tid + 3 * BLOCK] = mn3;
}

// kernel2: 128 blocks x 256 threads over (b,n) items; combine ref-split mins,
// add |q|^2 for both directions, weight, block-reduce.
__global__ __launch_bounds__(256) void chamfer_combine_kernel(
    const float* __restrict__ pred,
    const float* __restrict__ gt,
    const float* __restrict__ weight)
{
    const int i  = blockIdx.x * 256 + threadIdx.x;   // 0..32767
    const int b  = i >> 13;
    const int n  = i & (N - 1);
    const int qt = n >> 9;
    const int ql = n & (QPB - 1);
    const float INF = __int_as_float(0x7f800000);

    const int base0 = (b * 2 + 0) * (QT * RS * QPB) + qt * (RS * QPB) + ql;
    const int base1 = (b * 2 + 1) * (QT * RS * QPB) + qt * (RS * QPB) + ql;
    float m0 = INF, m1 = INF;
#pragma unroll
    for (int r = 0; r < RS; r++) {
        m0 = fminf(m0, g_pmin[base0 + r * QPB]);
        m1 = fminf(m1, g_pmin[base1 + r * QPB]);
    }

    const float* P = pred   + (size_t)(b * N + n) * 3;
    const float* G = gt     + (size_t)(b * N + n) * 3;
    const float* W = weight + (size_t)(b * N + n) * 3;
    const float p2p = P[0] * P[0] + P[1] * P[1] + P[2] * P[2];
    const float p2g = G[0] * G[0] + G[1] * G[1] + G[2] * G[2];
    const float w   = (W[0] + W[1] + W[2]) * (1.0f / 3.0f);

    float v = ((p2p + m0) + (p2g + m1)) * w;

    __shared__ float red[256];
    red[threadIdx.x] = v;
    __syncthreads();
#pragma unroll
    for (int s = 128; s > 0; s >>= 1) {
        if (threadIdx.x < s) red[threadIdx.x] += red[threadIdx.x + s];
        __syncthreads();
    }
    if (threadIdx.x == 0) g_partial2[blockIdx.x] = red[0];
}

__global__ void chamfer_final_kernel(float* __restrict__ out)
{
    __shared__ float red[128];
    const int tid = threadIdx.x;
    red[tid] = g_partial2[tid];
    __syncthreads();
#pragma unroll
    for (int s = 64; s > 0; s >>= 1) {
        if (tid < s) red[tid] += red[tid + s];
        __syncthreads();
    }
    if (tid == 0) out[0] = red[0] * (1.0f / (float)(B * N));
}

extern "C" void kernel_launch(void* const* d_in, const int* in_sizes, int n_in,
                              void* d_out, int out_size)
{
    const float* pred   = (const float*)d_in[0];
    const float* gt     = (const float*)d_in[1];
    const float* weight = (const float*)d_in[2];
    float* out = (float*)d_out;

    chamfer_min_kernel<<<GRID1, BLOCK>>>(pred, gt);
    chamfer_combine_kernel<<<128, 256>>>(pred, gt, weight);
    chamfer_final_kernel<<<1, 128>>>(out);
}

// round 7
// speedup vs baseline: 1.7816x; 1.0785x over previous
#include <cuda_runtime.h>
#include <cuda_bf16.h>
#include <cstdint>

// ChamferLoss B=4, N=8192, D=3.  (build r6a)
// dist(n,m) = |q_n|^2 + (|g_m|^2 - 2 q_n . g_m). Inner loop computes
// s = g2 - 2 q.g with packed fma.rn.f32x2 (2 query points per op); |q|^2 is
// added after the min. Refs staged in shared pre-duplicated:
//   (-2gx,-2gx)(-2gy,-2gy) | (-2gz,-2gz)(g2,g2)
// so two LDS.128 yield ready-to-use packed operands for 8 query points.
//
// PPT=8 queries/thread: 12 FFMA2/iter = 24 fma-pipe cycles vs ~22 issue
// slots, so the fma pipe binds. 4 independent FMA chains/iter give ILP.
//
// Decomposition: 4 batches x 2 dirs x 8 query-tiles(1024) x 16 ref-splits(512)
// = 1024 uniform blocks (1.2% wave imbalance on 148 SMs). Partial mins go to
// __device__ scratch; kernel2 combines mins + |q|^2 + weights + block-reduce;
// kernel3 does the final fixed-order sum. Deterministic, allocation-free,
// graph-capturable.

constexpr int B = 4;
constexpr int N = 8192;
constexpr int BLOCK = 128;
constexpr int PPT = 8;                    // queries per thread (4 f32x2 pairs)
constexpr int NPAIR = PPT / 2;            // 4
constexpr int QPB = BLOCK * PPT;          // 1024 queries per block
constexpr int QT  = N / QPB;              // 8 query tiles
constexpr int RS  = 16;                   // ref splits
constexpr int REFS_PER_RS = N / RS;       // 512
constexpr int TS  = 512;                  // refs per shared tile (16 KB)
constexpr int GRID1 = B * 2 * QT * RS;    // 1024 blocks
constexpr int NBD = B * 2;

// pmin layout: [bd(8)][qt(8)][rs(16)][1024]; block bx = (bd*QT+qt)*RS+rs
__device__ float g_pmin[NBD * QT * RS * QPB];
__device__ float g_partial2[128];

__device__ __forceinline__ unsigned long long fma2(
    unsigned long long a, unsigned long long b, unsigned long long c)
{
    unsigned long long d;
    asm("fma.rn.f32x2 %0, %1, %2, %3;" : "=l"(d) : "l"(a), "l"(b), "l"(c));
    return d;
}

__device__ __forceinline__ unsigned long long pack2(float lo, float hi)
{
    unsigned long long d;
    asm("mov.b64 %0, {%1, %2};" : "=l"(d) : "f"(lo), "f"(hi));
    return d;
}

__device__ __forceinline__ void unpack2(unsigned long long v, float& lo, float& hi)
{
    asm("mov.b64 {%0, %1}, %2;" : "=f"(lo), "=f"(hi) : "l"(v));
}

__global__ __launch_bounds__(BLOCK) void chamfer_min_kernel(
    const float* __restrict__ pred,
    const float* __restrict__ gt)
{
    const int bx  = blockIdx.x;
    const int rs  = bx & (RS - 1);
    const int qt  = (bx >> 4) & (QT - 1);
    const int bd  = bx >> 7;
    const int dir = bd & 1;
    const int b   = bd >> 1;

    const float* __restrict__ Q = (dir ? gt   : pred) + (size_t)(b * N) * 3;
    const float* __restrict__ R = (dir ? pred : gt  ) + (size_t)(b * N) * 3;

    __shared__ unsigned long long sh[4 * TS];

    const int tid = threadIdx.x;
    const float INF = __int_as_float(0x7f800000);

    // Queries: qt*1024 + tid + k*128, k=0..7; pair pp packs (k=2pp, k=2pp+1).
    unsigned long long qx[NPAIR], qy[NPAIR], qz[NPAIR];
#pragma unroll
    for (int pp = 0; pp < NPAIR; pp++) {
        const int qa = qt * QPB + tid + (2 * pp) * BLOCK;
        const int qb = qa + BLOCK;
        qx[pp] = pack2(Q[3 * qa + 0], Q[3 * qb + 0]);
        qy[pp] = pack2(Q[3 * qa + 1], Q[3 * qb + 1]);
        qz[pp] = pack2(Q[3 * qa + 2], Q[3 * qb + 2]);
    }

    float mn[PPT];
#pragma unroll
    for (int k = 0; k < PPT; k++) mn[k] = INF;

    // Stage this block's ref split (512 refs = exactly one shared tile).
    const int t0 = rs * REFS_PER_RS;
    for (int j = tid; j < TS; j += BLOCK) {
        const float* rp = R + 3 * (t0 + j);
        const float gx = rp[0];
        const float gy = rp[1];
        const float gz = rp[2];
        const float g2 = fmaf(gx, gx, fmaf(gy, gy, gz * gz));
        unsigned long long* sp = sh + 4 * j;
        sp[0] = pack2(-2.0f * gx, -2.0f * gx);
        sp[1] = pack2(-2.0f * gy, -2.0f * gy);
        sp[2] = pack2(-2.0f * gz, -2.0f * gz);
        sp[3] = pack2(g2, g2);
    }
    __syncthreads();

    const ulonglong2* __restrict__ sh2 = reinterpret_cast<const ulonglong2*>(sh);
#pragma unroll 8
    for (int j = 0; j < TS; j++) {
        const ulonglong2 hxy = sh2[2 * j];      // (hxx, hyy)
        const ulonglong2 hzw = sh2[2 * j + 1];  // (hzz, hww)

        unsigned long long s[NPAIR];
#pragma unroll
        for (int pp = 0; pp < NPAIR; pp++) s[pp] = fma2(qx[pp], hxy.x, hzw.y);
#pragma unroll
        for (int pp = 0; pp < NPAIR; pp++) s[pp] = fma2(qy[pp], hxy.y, s[pp]);
#pragma unroll
        for (int pp = 0; pp < NPAIR; pp++) s[pp] = fma2(qz[pp], hzw.x, s[pp]);

#pragma unroll
        for (int pp = 0; pp < NPAIR; pp++) {
            float lo, hi;
            unpack2(s[pp], lo, hi);
            mn[2 * pp]     = fminf(mn[2 * pp], lo);
            mn[2 * pp + 1] = fminf(mn[2 * pp + 1], hi);
        }
    }

    float* __restrict__ out = g_pmin + (size_t)bx * QPB;
#pragma unroll
    for (int k = 0; k < PPT; k++)
        out[tid + k * BLOCK] = mn[k];
}

// kernel2: 128 blocks x 256 threads over (b,n); combine ref-split mins,
// add |q|^2 for both directions, weight, block-reduce.
__global__ __launch_bounds__(256) void chamfer_combine_kernel(
    const float* __restrict__ pred,
    const float* __restrict__ gt,
    const float* __restrict__ weight)
{
    const int i  = blockIdx.x * 256 + threadIdx.x;   // 0..32767
    const int b  = i >> 13;
    const int n  = i & (N - 1);
    const int qt = n >> 10;            // n / QPB
    const int ql = n & (QPB - 1);
    const float INF = __int_as_float(0x7f800000);

    const int base0 = ((b * 2 + 0) * QT + qt) * (RS * QPB) + ql;
    const int base1 = ((b * 2 + 1) * QT + qt) * (RS * QPB) + ql;
    float m0 = INF, m1 = INF;
#pragma unroll
    for (int r = 0; r < RS; r++) {
        m0 = fminf(m0, g_pmin[base0 + r * QPB]);
        m1 = fminf(m1, g_pmin[base1 + r * QPB]);
    }

    const float* P = pred   + (size_t)(b * N + n) * 3;
    const float* G = gt     + (size_t)(b * N + n) * 3;
    const float* W = weight + (size_t)(b * N + n) * 3;
    const float p2p = P[0] * P[0] + P[1] * P[1] + P[2] * P[2];
    const float p2g = G[0] * G[0] + G[1] * G[1] + G[2] * G[2];
    const float w   = (W[0] + W[1] + W[2]) * (1.0f / 3.0f);

    const float v = ((p2p + m0) + (p2g + m1)) * w;

    __shared__ float red[256];
    red[threadIdx.x] = v;
    __syncthreads();
#pragma unroll
    for (int s = 128; s > 0; s >>= 1) {
        if (threadIdx.x < s) red[threadIdx.x] += red[threadIdx.x + s];
        __syncthreads();
    }
    if (threadIdx.x == 0) g_partial2[blockIdx.x] = red[0];
}

__global__ void chamfer_final_kernel(float* __restrict__ out)
{
    __shared__ float red[128];
    const int tid = threadIdx.x;
    red[tid] = g_partial2[tid];
    __syncthreads();
#pragma unroll
    for (int s = 64; s > 0; s >>= 1) {
        if (tid < s) red[tid] += red[tid + s];
        __syncthreads();
    }
    if (tid == 0) out[0] = red[0] * (1.0f / (float)(B * N));
}

extern "C" void kernel_launch(void* const* d_in, const int* in_sizes, int n_in,
                              void* d_out, int out_size)
{
    const float* pred   = (const float*)d_in[0];
    const float* gt     = (const float*)d_in[1];
    const float* weight = (const float*)d_in[2];
    float* out = (float*)d_out;

    chamfer_min_kernel<<<GRID1, BLOCK>>>(pred, gt);
    chamfer_combine_kernel<<<128, 256>>>(pred, gt, weight);
    chamfer_final_kernel<<<1, 128>>>(out);
}